// round 15
// baseline (speedup 1.0000x reference)
#include <cuda_runtime.h>
#include <stdint.h>
#include <math.h>

#define NEGV  -1e30f
#define SWT   128         // sw threads; thread owns 4 cols x 4 rows per step
#define STEPS 255         // 128 row-groups + 127 skew
#define FUU   256         // feed u-rows
#define LOG2E 1.4426950408889634f
#define LN2   0.6931471805599453f

// ---- static device scratch ----
__device__ float  g_S[4 * 512 * 512];          // plain score matrices
__device__ float  g_n2[2 * 4 * 512];           // row norms
__device__ float4 g_Sf4[4 * FUU * 512];        // skewed S feed [u][r][t], base-2
__device__ float4 g_gof4[FUU * 512];           // skewed go feed
__device__ float4 g_gef4[FUU * 512];           // skewed ge feed
__device__ float4 g_Df4[4 * FUU * 512];        // skewed D output [u][r][t]
__device__ float  g_pm[256], g_ps[256];        // LSE partials (64 per batch)

__device__ __forceinline__ float ex2a(float x) {
    float r; asm("ex2.approx.ftz.f32 %0, %1;" : "=f"(r) : "f"(x)); return r;
}
__device__ __forceinline__ float lg2a(float x) {
    float r; asm("lg2.approx.ftz.f32 %0, %1;" : "=f"(r) : "f"(x)); return r;
}
__device__ __forceinline__ float lse2b(float a, float b) {
    float m = fmaxf(a, b), n = fminf(a, b);
    return m + lg2a(1.0f + ex2a(n - m));
}
__device__ __forceinline__ float lse3b(float a, float b) {   // LSE(a,b,0)
    float m = fmaxf(fmaxf(a, b), 0.f);
    return m + lg2a(ex2a(a - m) + ex2a(b - m) + ex2a(-m));
}

// ================= norms =================
__global__ void norm_kernel(const float* __restrict__ x, const float* __restrict__ y) {
    int w = (blockIdx.x * blockDim.x + threadIdx.x) >> 5;
    int lane = threadIdx.x & 31;
    #pragma unroll
    for (int s = 0; s < 16; s++) {
        int row = w + s * 256;
        const float* p = (row < 2048) ? (x + row * 128) : (y + (row - 2048) * 128);
        float v0 = p[lane], v1 = p[lane + 32], v2 = p[lane + 64], v3 = p[lane + 96];
        float sum = v0 * v0 + v1 * v1 + v2 * v2 + v3 * v3;
        #pragma unroll
        for (int o = 16; o > 0; o >>= 1) sum += __shfl_xor_sync(0xffffffffu, sum, o);
        if (lane == 0) g_n2[row] = sum;
    }
}

// ================= S = x2 + y2 - 2 x.y  (64x64 tiles) =================
__global__ void __launch_bounds__(256) dist_kernel(const float* __restrict__ x,
                                                   const float* __restrict__ y) {
    int b = blockIdx.z;
    int i0 = blockIdx.y * 64, j0 = blockIdx.x * 64;
    const float* xb = x + (b * 512 + i0) * 128;
    const float* yb = y + (b * 512 + j0) * 128;
    __shared__ float xs[16][64];
    __shared__ float ys[16][64];
    int tid = threadIdx.x;
    int tx = tid & 15, ty = tid >> 4;
    float acc[4][4];
    #pragma unroll
    for (int r = 0; r < 4; r++)
        #pragma unroll
        for (int c = 0; c < 4; c++) acc[r][c] = 0.f;

    for (int kc = 0; kc < 128; kc += 16) {
        __syncthreads();
        #pragma unroll
        for (int l = 0; l < 4; l++) {
            int e = tid + l * 256;
            int r = e >> 4, kk = e & 15;
            xs[kk][r] = xb[r * 128 + kc + kk];
            ys[kk][r] = yb[r * 128 + kc + kk];
        }
        __syncthreads();
        #pragma unroll
        for (int kk = 0; kk < 16; kk++) {
            float4 a  = *(const float4*)&xs[kk][ty * 4];
            float4 bv = *(const float4*)&ys[kk][tx * 4];
            float ar[4] = {a.x, a.y, a.z, a.w};
            float br[4] = {bv.x, bv.y, bv.z, bv.w};
            #pragma unroll
            for (int r = 0; r < 4; r++)
                #pragma unroll
                for (int c = 0; c < 4; c++)
                    acc[r][c] = fmaf(ar[r], br[c], acc[r][c]);
        }
    }
    float x2[4], y2[4];
    #pragma unroll
    for (int r = 0; r < 4; r++) x2[r] = g_n2[b * 512 + i0 + ty * 4 + r];
    #pragma unroll
    for (int c = 0; c < 4; c++) y2[c] = g_n2[2048 + b * 512 + j0 + tx * 4 + c];
    float* Sb = g_S + b * 262144;
    #pragma unroll
    for (int r = 0; r < 4; r++) {
        float4 o;
        o.x = x2[r] + y2[0] - 2.f * acc[r][0];
        o.y = x2[r] + y2[1] - 2.f * acc[r][1];
        o.z = x2[r] + y2[2] - 2.f * acc[r][2];
        o.w = x2[r] + y2[3] - 2.f * acc[r][3];
        *(float4*)&Sb[(i0 + ty * 4 + r) * 512 + j0 + tx * 4] = o;
    }
}

// ================= reskew: M -> F[u][r][t] (float4 over c), base-2 ==============
// element (u,r,t,c) = LOG2E * M[4(u-t)+r][4t+c], valid 0 <= u-t < 128.
// Tiles: d-tile 16 (8 tiles) x t-tile 32 (4 tiles); u = d0+dd + t0+tl.
__global__ void __launch_bounds__(256) reskew_kernel(const float* __restrict__ go,
                                                     const float* __restrict__ ge) {
    int m = blockIdx.y;                 // 0..3 = S batches, 4 = go, 5 = ge
    int dt = blockIdx.x >> 2;           // 0..7
    int tt = blockIdx.x & 3;            // 0..3
    const float* src = (m < 4) ? (g_S + m * 262144) : ((m == 4) ? go : ge);
    float4* dst = (m < 4) ? (g_Sf4 + m * (FUU * 512)) : ((m == 4) ? g_gof4 : g_gef4);
    int d0 = dt * 16, t0 = tt * 32;
    __shared__ __align__(16) float sm[64][132];
    int tid = threadIdx.x;
    #pragma unroll
    for (int l = 0; l < 32; l++) {
        int e = tid + l * 256;          // 8192 = 64 rows x 128 cols
        int rr = e >> 7, cc = e & 127;
        sm[rr][cc] = LOG2E * src[(4 * d0 + rr) * 512 + 4 * t0 + cc];
    }
    __syncthreads();
    #pragma unroll
    for (int l = 0; l < 8; l++) {
        int e = tid + l * 256;          // 2048 float4
        int r = e & 3, tl = (e >> 2) & 31, dd = e >> 7;
        int u = d0 + dd + t0 + tl;
        dst[(u * 4 + r) * 128 + t0 + tl] = *(const float4*)&sm[4 * dd + r][4 * tl];
    }
}

// ================= wavefront soft-SW; 1 CTA/batch, 4 cols x 4 rows/thread =======
__global__ __launch_bounds__(SWT, 1) void sw_kernel() {
    const int b = blockIdx.x;
    const int t = threadIdx.x, lane = t & 31, warp = t >> 5;
    const float4* S4  = g_Sf4 + b * (FUU * 512);
    const float4* go4 = g_gof4;
    const float4* ge4 = g_gef4;
    float4* Df4 = g_Df4 + b * (FUU * 512);

    __shared__ float sh[2][4][12];      // [parity][warp][BD0-3, BI0-3, Bg0-3]
    if (t < 96) {
        int q = t % 12;
        ((float*)sh)[t] = (q >= 8) ? 0.f : NEGV;
    }
    __syncthreads();

    // carried state: row-3 of previous block, per column
    float hR[4], iyR[4], gR[4];
    #pragma unroll
    for (int c = 0; c < 4; c++) { hR[c] = NEGV; iyR[c] = NEGV; gR[c] = 0.f; }
    // boundary (own col 3) per row
    float BD[4], BI[4], Bg[4];
    #pragma unroll
    for (int r = 0; r < 4; r++) { BD[r] = NEGV; BI[r] = NEGV; Bg[r] = 0.f; }
    float gstale = 0.f;

    float4 sP[4], goP[4], geP[4];
    #pragma unroll
    for (int r = 0; r < 4; r++) {
        sP[r] = S4[r * 128 + t]; goP[r] = go4[r * 128 + t]; geP[r] = ge4[r * 128 + t];
    }

    auto step = [&](int u, int par) {
        float4 sC[4], goC[4], geC[4];
        #pragma unroll
        for (int r = 0; r < 4; r++) { sC[r] = sP[r]; goC[r] = goP[r]; geC[r] = geP[r]; }
        {
            int base = (u + 1) * 512 + t;
            #pragma unroll
            for (int r = 0; r < 4; r++) {
                sP[r] = S4[base + r * 128];
                goP[r] = go4[base + r * 128];
                geP[r] = ge4[base + r * 128];
            }
        }
        // neighbor exchange: 12 values (prev-step boundary of thread t-1)
        float nD[4], nI[4], ng[4];
        #pragma unroll
        for (int r = 0; r < 4; r++) {
            nD[r] = __shfl_up_sync(0xffffffffu, BD[r], 1);
            nI[r] = __shfl_up_sync(0xffffffffu, BI[r], 1);
            ng[r] = __shfl_up_sync(0xffffffffu, Bg[r], 1);
        }
        if (lane == 0) {
            if (warp > 0) {
                int pp = par ^ 1;
                #pragma unroll
                for (int r = 0; r < 4; r++) {
                    nD[r] = sh[pp][warp - 1][r];
                    nI[r] = sh[pp][warp - 1][4 + r];
                    ng[r] = sh[pp][warp - 1][8 + r];
                }
            } else {
                #pragma unroll
                for (int r = 0; r < 4; r++) { nD[r] = NEGV; nI[r] = NEGV; ng[r] = 0.f; }
            }
        }
        int d = u - t;
        bool act = (d >= 0) && (d < 128);
        if (act) {
            float sA[4][4], goA[4][4], geA[4][4];
            #pragma unroll
            for (int r = 0; r < 4; r++) {
                sA[r][0] = sC[r].x;  sA[r][1] = sC[r].y;  sA[r][2] = sC[r].z;  sA[r][3] = sC[r].w;
                goA[r][0] = goC[r].x; goA[r][1] = goC[r].y; goA[r][2] = goC[r].z; goA[r][3] = goC[r].w;
                geA[r][0] = geC[r].x; geA[r][1] = geC[r].y; geA[r][2] = geC[r].z; geA[r][3] = geC[r].w;
            }
            int obase = u * 512 + t;
            #pragma unroll
            for (int r = 0; r < 4; r++) {
                float dL = nD[r], ixL = nI[r];
                float gdiag = (r == 0) ? gstale : ng[r - 1];
                float dOut[4];
                #pragma unroll
                for (int c = 0; c < 4; c++) {
                    float go_ = goA[r][c], ge_ = geA[r][c];
                    float ix = lse2b(dL - go_, ixL - ge_);
                    float iy = lse2b(hR[c] - go_, iyR[c] - ge_);
                    float dd = sA[r][c] + gdiag;
                    float h  = lse2b(dd, ix);
                    float g  = lse3b(h, iy);
                    gdiag = gR[c];              // old g (row r-1, col c) for cell (r, c+1)
                    hR[c] = h; iyR[c] = iy; gR[c] = g;
                    dOut[c] = dd;
                    dL = dd; ixL = ix;
                    if (c == 3) { BD[r] = dd; BI[r] = ix; Bg[r] = g; }
                }
                Df4[obase + r * 128] = make_float4(dOut[0], dOut[1], dOut[2], dOut[3]);
            }
        }
        gstale = ng[3];
        if (lane == 31) {
            #pragma unroll
            for (int r = 0; r < 4; r++) {
                sh[par][warp][r] = BD[r];
                sh[par][warp][4 + r] = BI[r];
                sh[par][warp][8 + r] = Bg[r];
            }
        }
        __syncthreads();
    };

    for (int i = 0; i < 254; i += 2) {
        step(i, 0);
        step(i + 1, 1);
    }
    step(254, 0);
}

// ================= LSE over valid D slots (base-2 domain) =================
__global__ void lse_part() {
    int blk = blockIdx.x, b = blockIdx.y;    // 64 x 4
    const float4* Dv = g_Df4 + b * (FUU * 512);
    int tid = threadIdx.x;
    float m = NEGV, s = 0.f;
    #pragma unroll
    for (int l = 0; l < 8; l++) {
        int slot = blk * 2048 + tid + l * 256;    // 64*2048 = 131072 = 256*4*128
        int u = slot >> 9, tc = slot & 127;
        int d = u - tc;
        if (d >= 0 && d < 128) {
            float4 v = Dv[slot];
            float m4 = fmaxf(fmaxf(v.x, v.y), fmaxf(v.z, v.w));
            float nm = fmaxf(m, m4);
            s = s * ex2a(m - nm) + ex2a(v.x - nm) + ex2a(v.y - nm)
                                 + ex2a(v.z - nm) + ex2a(v.w - nm);
            m = nm;
        }
    }
    __shared__ float sm[256], ss[256];
    sm[tid] = m; ss[tid] = s;
    __syncthreads();
    for (int o = 128; o > 0; o >>= 1) {
        if (tid < o) {
            float m2 = sm[tid + o], s2 = ss[tid + o];
            float nm = fmaxf(sm[tid], m2);
            ss[tid] = ss[tid] * ex2a(sm[tid] - nm) + s2 * ex2a(m2 - nm);
            sm[tid] = nm;
        }
        __syncthreads();
    }
    if (tid == 0) { g_pm[b * 64 + blk] = sm[0]; g_ps[b * 64 + blk] = ss[0]; }
}

__global__ void lse_final(float* __restrict__ out) {
    int t = threadIdx.x;              // 256
    int b = t >> 6, r = t & 63;
    __shared__ float sm[256], ss[256], vv[4];
    sm[t] = g_pm[b * 64 + r]; ss[t] = g_ps[b * 64 + r];
    __syncthreads();
    for (int o = 32; o > 0; o >>= 1) {
        if (r < o) {
            float m2 = sm[t + o], s2 = ss[t + o];
            float nm = fmaxf(sm[t], m2);
            ss[t] = ss[t] * ex2a(sm[t] - nm) + s2 * ex2a(m2 - nm);
            sm[t] = nm;
        }
        __syncthreads();
    }
    if (r == 0) vv[b] = LN2 * (sm[t] + lg2a(ss[t]));
    __syncthreads();
    if (t == 0) out[0] = 0.25f * (vv[0] + vv[1] + vv[2] + vv[3]);
}

// ================= deskew: Df[u][r][t] -> probas (inverse of reskew) ============
__global__ void __launch_bounds__(256) deskew_kernel(float* __restrict__ out) {
    int b = blockIdx.y;
    int dt = blockIdx.x >> 2, tt = blockIdx.x & 3;
    const float4* Df = g_Df4 + b * (FUU * 512);
    int d0 = dt * 16, t0 = tt * 32;
    __shared__ __align__(16) float sm[64][132];
    int tid = threadIdx.x;
    #pragma unroll
    for (int l = 0; l < 8; l++) {
        int e = tid + l * 256;          // 2048 float4
        int r = e & 3, tl = (e >> 2) & 31, dd = e >> 7;
        int u = d0 + dd + t0 + tl;
        *(float4*)&sm[4 * dd + r][4 * tl] = Df[(u * 4 + r) * 128 + t0 + tl];
    }
    __syncthreads();
    float* ob = out + 1 + b * 262144;
    #pragma unroll
    for (int l = 0; l < 32; l++) {
        int e = tid + l * 256;          // 8192 floats
        int rr = e >> 7, cc = e & 127;
        ob[(4 * d0 + rr) * 512 + 4 * t0 + cc] = LN2 * sm[rr][cc];
    }
}

// ================= launcher =================
extern "C" void kernel_launch(void* const* d_in, const int* in_sizes, int n_in,
                              void* d_out, int out_size) {
    const float* x  = (const float*)d_in[0];
    const float* y  = (const float*)d_in[1];
    const float* go = (const float*)d_in[2];
    const float* ge = (const float*)d_in[3];
    float* out = (float*)d_out;

    norm_kernel<<<32, 256>>>(x, y);
    dist_kernel<<<dim3(8, 8, 4), 256>>>(x, y);
    reskew_kernel<<<dim3(32, 6), 256>>>(go, ge);
    sw_kernel<<<4, SWT>>>();
    lse_part<<<dim3(64, 4), 256>>>();
    deskew_kernel<<<dim3(32, 4), 256>>>(out);
    lse_final<<<1, 256>>>(out);
}